// round 15
// baseline (speedup 1.0000x reference)
#include <cuda_runtime.h>
#include <cuda_fp16.h>
#include <cstdint>
#include <cstddef>

#define N_NODES 16384
#define E_EDGES 262144
#define F_IN    1024
#define H1_DIM  256
#define NZ_DIM  64

// ---------------- scratch ----------------------------------------------------
__device__ __half g_xh [N_NODES * F_IN];
__device__ __half g_s1h[N_NODES * H1_DIM];
__device__ __half g_h1h[N_NODES * H1_DIM];
__device__ __half g_s2h[N_NODES * NZ_DIM];
__device__ __half g_w1t[H1_DIM * F_IN];
__device__ __half g_w2t[NZ_DIM * H1_DIM];
__device__ __half g_zrh[N_NODES * NZ_DIM];
__device__ int    g_off   [N_NODES + 1];
__device__ int    g_cursor[N_NODES];
__device__ int2   g_srcw  [E_EDGES];

// ---------------- helpers -----------------------------------------------------
__device__ __forceinline__ void cp16(uint32_t s, const void* g) {
    asm volatile("cp.async.cg.shared.global [%0], [%1], 16;\n" ::"r"(s), "l"(g));
}
__device__ __forceinline__ void cp_commit() {
    asm volatile("cp.async.commit_group;\n");
}
template <int N>
__device__ __forceinline__ void cp_wait() {
    asm volatile("cp.async.wait_group %0;\n" ::"n"(N));
}
__device__ __forceinline__ uint32_t pack_h2(float lo, float hi) {
    __half2 h = __floats2half2_rn(lo, hi);
    return *reinterpret_cast<uint32_t*>(&h);
}
__device__ __forceinline__ void mma_f16(float (&d)[4], const uint32_t (&a)[4],
                                        const uint32_t (&b)[2]) {
    asm volatile(
        "mma.sync.aligned.m16n8k16.row.col.f32.f16.f16.f32 "
        "{%0,%1,%2,%3}, {%4,%5,%6,%7}, {%8,%9}, {%0,%1,%2,%3};"
        : "+f"(d[0]), "+f"(d[1]), "+f"(d[2]), "+f"(d[3])
        : "r"(a[0]), "r"(a[1]), "r"(a[2]), "r"(a[3]), "r"(b[0]), "r"(b[1]));
}
__device__ __forceinline__ void ldsm_x4(uint32_t& r0, uint32_t& r1,
                                        uint32_t& r2, uint32_t& r3, uint32_t a) {
    asm volatile("ldmatrix.sync.aligned.m8n8.x4.shared.b16 {%0,%1,%2,%3}, [%4];"
                 : "=r"(r0), "=r"(r1), "=r"(r2), "=r"(r3) : "r"(a));
}
__device__ __forceinline__ void st_cs1(float* p, float v) {
    asm volatile("st.global.cs.f32 [%0], %1;" ::"l"(p), "f"(v) : "memory");
}
__device__ __forceinline__ void st_cs2(float* p, float v0, float v1) {
    asm volatile("st.global.cs.v2.f32 [%0], {%1, %2};"
                 ::"l"(p), "f"(v0), "f"(v1) : "memory");
}

// ---------------- x -> fp16 convert --------------------------------------------
__global__ void k_x2h(const float4* __restrict__ in, uint2* __restrict__ out) {
    int i = blockIdx.x * blockDim.x + threadIdx.x;
    float4 v = in[i];
    out[i] = make_uint2(pack_h2(v.x, v.y), pack_h2(v.z, v.w));
}

// ---------------- CSR build ----------------------------------------------------
__global__ void k_zero_counts() {
    int i = blockIdx.x * blockDim.x + threadIdx.x;
    ((int4*)g_cursor)[i] = make_int4(0, 0, 0, 0);
}
__global__ void k_hist(const int* __restrict__ ei) {
    int e = blockIdx.x * blockDim.x + threadIdx.x;
    if (e < E_EDGES) atomicAdd(&g_cursor[ei[E_EDGES + e]], 1);
}
__global__ void k_scan() {
    __shared__ int part[256];
    const int t = threadIdx.x;
    const int base = t * (N_NODES / 256);
    int s = 0;
#pragma unroll
    for (int j = 0; j < N_NODES / 256; j++) s += g_cursor[base + j];
    part[t] = s;
    __syncthreads();
    for (int off = 1; off < 256; off <<= 1) {
        int v = (t >= off) ? part[t - off] : 0;
        __syncthreads();
        part[t] += v;
        __syncthreads();
    }
    int run = part[t] - s;
#pragma unroll
    for (int j = 0; j < N_NODES / 256; j++) {
        int idx = base + j;
        int c = g_cursor[idx];
        g_off[idx] = run;
        g_cursor[idx] = run;
        run += c;
    }
    if (t == 255) g_off[N_NODES] = run;
}
__global__ void k_scatter(const int* __restrict__ ei, const float* __restrict__ ew) {
    int e = blockIdx.x * blockDim.x + threadIdx.x;
    if (e < E_EDGES) {
        int d = ei[E_EDGES + e];
        int p = atomicAdd(&g_cursor[d], 1);
        g_srcw[p] = make_int2(ei[e], __float_as_int(ew[e]));
    }
}

// ---------------- weight transpose -> fp16 -------------------------------------
__global__ void k_transpose_h(const float* __restrict__ in, __half* __restrict__ out,
                              int R, int C) {
    __shared__ float tile[32][33];
    const int bx = blockIdx.x * 32;
    const int by = blockIdx.y * 32;
    const int x = threadIdx.x, y0 = threadIdx.y;
#pragma unroll
    for (int j = y0; j < 32; j += 8)
        tile[j][x] = in[(size_t)(by + j) * C + bx + x];
    __syncthreads();
#pragma unroll
    for (int j = y0; j < 32; j += 8)
        out[(size_t)(bx + j) * R + by + x] = __float2half_rn(tile[x][j]);
}

// ---------------- SpMM + ReLU (half2 lanes, fp32 accumulate) -------------------
__global__ void __launch_bounds__(256) k_spmm_relu_256h2(
    const __half2* __restrict__ in2, __half2* __restrict__ out2) {
    __shared__ int2 se[2][128];
    __shared__ int sdeg[2];
    const int t    = threadIdx.x;
    const int sub  = t >> 7;
    const int lane = t & 127;
    const int row  = blockIdx.x * 2 + sub;
    if (t < 2) sdeg[t] = g_off[blockIdx.x * 2 + t + 1] - g_off[blockIdx.x * 2 + t];
    __syncthreads();
    const int beg = g_off[row];
    const int deg = sdeg[sub];
    const int nch = (max(sdeg[0], sdeg[1]) + 127) >> 7;
    float ax = 0.f, ay = 0.f;
    for (int ch = 0; ch < nch; ch++) {
        int m = min(128, deg - ch * 128);
        __syncthreads();
        if (lane < m) se[sub][lane] = g_srcw[beg + ch * 128 + lane];
        __syncthreads();
        int j = 0;
        for (; j + 8 <= m; j += 8) {
            int2 v[8];
            float2 f[8];
#pragma unroll
            for (int u = 0; u < 8; u++) v[u] = se[sub][j + u];
#pragma unroll
            for (int u = 0; u < 8; u++)
                f[u] = __half22float2(__ldg(&in2[(size_t)v[u].x * 128 + lane]));
#pragma unroll
            for (int u = 0; u < 8; u++) {
                float w = __int_as_float(v[u].y);
                ax += w * f[u].x;
                ay += w * f[u].y;
            }
        }
        for (; j < m; j++) {
            int2 v = se[sub][j];
            float2 f = __half22float2(__ldg(&in2[(size_t)v.x * 128 + lane]));
            float w = __int_as_float(v.y);
            ax += w * f.x;
            ay += w * f.y;
        }
    }
    out2[(size_t)row * 128 + lane] = __floats2half2_rn(fmaxf(ax, 0.f), fmaxf(ay, 0.f));
}

__global__ void __launch_bounds__(256) k_spmm_relu_64h2(
    const __half2* __restrict__ in2, float2* __restrict__ out2,
    __half2* __restrict__ outr2) {
    __shared__ int2 se[8][32];
    __shared__ int sdeg[8];
    const int t    = threadIdx.x;
    const int sub  = t >> 5;
    const int lane = t & 31;
    const int row  = blockIdx.x * 8 + sub;
    if (t < 8) sdeg[t] = g_off[blockIdx.x * 8 + t + 1] - g_off[blockIdx.x * 8 + t];
    __syncthreads();
    const int beg = g_off[row];
    const int deg = sdeg[sub];
    int mx = sdeg[0];
#pragma unroll
    for (int q = 1; q < 8; q++) mx = max(mx, sdeg[q]);
    const int nch = (mx + 31) >> 5;
    float ax = 0.f, ay = 0.f;
    for (int ch = 0; ch < nch; ch++) {
        int m = min(32, deg - ch * 32);
        __syncthreads();
        if (lane < m) se[sub][lane] = g_srcw[beg + ch * 32 + lane];
        __syncthreads();
        int j = 0;
        for (; j + 8 <= m; j += 8) {
            int2 v[8];
            float2 f[8];
#pragma unroll
            for (int u = 0; u < 8; u++) v[u] = se[sub][j + u];
#pragma unroll
            for (int u = 0; u < 8; u++)
                f[u] = __half22float2(__ldg(&in2[(size_t)v[u].x * 32 + lane]));
#pragma unroll
            for (int u = 0; u < 8; u++) {
                float w = __int_as_float(v[u].y);
                ax += w * f[u].x;
                ay += w * f[u].y;
            }
        }
        for (; j < m; j++) {
            int2 v = se[sub][j];
            float2 f = __half22float2(__ldg(&in2[(size_t)v.x * 32 + lane]));
            float w = __int_as_float(v.y);
            ax += w * f.x;
            ay += w * f.y;
        }
    }
    float rx = fmaxf(ax, 0.f), ry = fmaxf(ay, 0.f);
    out2 [(size_t)row * 32 + lane] = make_float2(rx, ry);
    outr2[(size_t)row * 32 + lane] = __floats2half2_rn(rx, ry);
}

// ---------------- gemm1: BM=128 BN=128 BK=64, SW128 swizzle, 3 stages -----------
__global__ void __launch_bounds__(256, 2)
k_gemm1hh(const __half* __restrict__ A, const __half* __restrict__ Bt,
          __half* __restrict__ C) {
    constexpr int K = F_IN, Nc = H1_DIM;
    constexpr int STAGE = 16384;
    constexpr int STG = 3;
    constexpr int NT = K / 64;

    extern __shared__ __half smh[];
    const uint32_t smem_u32 = (uint32_t)__cvta_generic_to_shared(smh);
    const uint32_t bb0 = smem_u32 + STG * STAGE;

    const int tid  = threadIdx.x;
    const int warp = tid >> 5, lane = tid & 31;
    const int wr = warp >> 1, wc = warp & 1;
    const int bm0 = blockIdx.y * 128, bn0 = blockIdx.x * 128;
    const int g = lane >> 2, c = lane & 3;

    const int lr = lane & 7, q = lane >> 3;
    uint32_t baseA[2], colA, xormA[2];
#pragma unroll
    for (int mi = 0; mi < 2; mi++) {
        int row = wr * 32 + mi * 16 + lr + (q & 1) * 8;
        baseA[mi] = (uint32_t)row * 128u;
        xormA[mi] = (uint32_t)((row & 7) << 4);
    }
    colA = (uint32_t)((q >> 1) * 16);
    uint32_t baseB[4], colB, xormB[4];
#pragma unroll
    for (int ii = 0; ii < 4; ii++) {
        int row = wc * 64 + (2 * ii + (q >> 1)) * 8 + lr;
        baseB[ii] = (uint32_t)row * 128u;
        xormB[ii] = (uint32_t)((row & 7) << 4);
    }
    colB = (uint32_t)((q & 1) * 16);

    float acc[2][8][4];
#pragma unroll
    for (int mi = 0; mi < 2; mi++)
#pragma unroll
        for (int ni = 0; ni < 8; ni++)
#pragma unroll
            for (int j = 0; j < 4; j++) acc[mi][ni][j] = 0.f;

    auto load_tiles = [&](int kt, int st) {
        const __half* Ag = A + (size_t)bm0 * K + kt * 64;
        uint32_t abase = smem_u32 + (uint32_t)(st * STAGE);
#pragma unroll
        for (int i = 0; i < 4; i++) {
            int v = tid + i * 256;
            int r = v >> 3, ch = v & 7;
            uint32_t off = (uint32_t)(r * 128 + ch * 16);
            uint32_t sw  = off ^ (uint32_t)((r & 7) << 4);
            cp16(abase + sw, Ag + (size_t)r * K + ch * 8);
        }
        const __half* Bg = Bt + (size_t)bn0 * K + kt * 64;
        uint32_t bbase = bb0 + (uint32_t)(st * STAGE);
#pragma unroll
        for (int i = 0; i < 4; i++) {
            int v = tid + i * 256;
            int r = v >> 3, ch = v & 7;
            uint32_t off = (uint32_t)(r * 128 + ch * 16);
            uint32_t sw  = off ^ (uint32_t)((r & 7) << 4);
            cp16(bbase + sw, Bg + (size_t)r * K + ch * 8);
        }
    };

    load_tiles(0, 0);
    cp_commit();
    load_tiles(1, 1);
    cp_commit();

    int st = 0;
    for (int kt = 0; kt < NT; kt++) {
        cp_wait<1>();
        __syncthreads();

        int pf = kt + 2;
        if (pf < NT) load_tiles(pf, (st + 2) % STG);
        cp_commit();

        uint32_t abase = smem_u32 + (uint32_t)(st * STAGE);
        uint32_t bbase = bb0 + (uint32_t)(st * STAGE);
#pragma unroll
        for (int ks = 0; ks < 4; ks++) {
            const uint32_t kofs = ks * 32;
            uint32_t af[2][4];
            uint32_t bf[8][2];
#pragma unroll
            for (int mi = 0; mi < 2; mi++)
                ldsm_x4(af[mi][0], af[mi][1], af[mi][2], af[mi][3],
                        abase + baseA[mi] + ((colA + kofs) ^ xormA[mi]));
#pragma unroll
            for (int ii = 0; ii < 4; ii++)
                ldsm_x4(bf[2 * ii][0], bf[2 * ii][1], bf[2 * ii + 1][0],
                        bf[2 * ii + 1][1],
                        bbase + baseB[ii] + ((colB + kofs) ^ xormB[ii]));
#pragma unroll
            for (int mi = 0; mi < 2; mi++)
#pragma unroll
                for (int ni = 0; ni < 8; ni++)
                    mma_f16(acc[mi][ni], af[mi], bf[ni]);
        }
        st = (st + 1) % STG;
    }

    __syncthreads();
#pragma unroll
    for (int mi = 0; mi < 2; mi++)
#pragma unroll
        for (int ni = 0; ni < 8; ni++) {
            int r  = bm0 + wr * 32 + mi * 16 + g;
            int cc = bn0 + wc * 64 + ni * 8 + c * 2;
            *reinterpret_cast<uint32_t*>(&C[(size_t)r * Nc + cc]) =
                pack_h2(acc[mi][ni][0], acc[mi][ni][1]);
            *reinterpret_cast<uint32_t*>(&C[(size_t)(r + 8) * Nc + cc]) =
                pack_h2(acc[mi][ni][2], acc[mi][ni][3]);
        }
}

// ---------------- gemm2: single-shot (full K in smem, no loop barriers) --------
__global__ void __launch_bounds__(256, 2)
k_gemm2h(const __half* __restrict__ A, const __half* __restrict__ Bt,
         __half* __restrict__ C) {
    constexpr int K = H1_DIM, Nc = NZ_DIM;
    constexpr int P = 264;

    extern __shared__ __half smh[];
    const uint32_t smem_u32 = (uint32_t)__cvta_generic_to_shared(smh);
    const uint32_t bb0 = smem_u32 + (uint32_t)(128 * P) * 2u;

    const int tid  = threadIdx.x;
    const int warp = tid >> 5, lane = tid & 31;
    const int wr = warp >> 1, wc = warp & 1;
    const int bm0 = blockIdx.y * 128;
    const int g = lane >> 2, c = lane & 3;

    const int lr = lane & 7, q = lane >> 3;
    uint32_t offA[2], offB[2];
#pragma unroll
    for (int mi = 0; mi < 2; mi++) {
        int row = wr * 32 + mi * 16 + lr + (q & 1) * 8;
        int col = (q >> 1) * 8;
        offA[mi] = (uint32_t)(row * P + col) * 2u;
    }
#pragma unroll
    for (int ii = 0; ii < 2; ii++) {
        int row = wc * 32 + (2 * ii + (q >> 1)) * 8 + lr;
        int col = (q & 1) * 8;
        offB[ii] = (uint32_t)(row * P + col) * 2u;
    }

    {
        const __half* Ag = A + (size_t)bm0 * K;
#pragma unroll
        for (int i = 0; i < 16; i++) {
            int v = tid + i * 256;
            int r = v >> 5, ch = v & 31;
            cp16(smem_u32 + (uint32_t)(r * P + ch * 8) * 2u,
                 Ag + (size_t)r * K + ch * 8);
        }
#pragma unroll
        for (int i = 0; i < 8; i++) {
            int v = tid + i * 256;
            int r = v >> 5, ch = v & 31;
            cp16(bb0 + (uint32_t)(r * P + ch * 8) * 2u,
                 Bt + (size_t)r * K + ch * 8);
        }
    }
    cp_commit();

    float acc[2][4][4];
#pragma unroll
    for (int mi = 0; mi < 2; mi++)
#pragma unroll
        for (int ni = 0; ni < 4; ni++)
#pragma unroll
            for (int j = 0; j < 4; j++) acc[mi][ni][j] = 0.f;

    cp_wait<0>();
    __syncthreads();

#pragma unroll
    for (int kk = 0; kk < K / 16; kk++) {
        const uint32_t kofs = (uint32_t)(kk * 16) * 2u;
        uint32_t af[2][4];
        uint32_t bf[4][2];
        ldsm_x4(af[0][0], af[0][1], af[0][2], af[0][3],
                smem_u32 + offA[0] + kofs);
        ldsm_x4(af[1][0], af[1][1], af[1][2], af[1][3],
                smem_u32 + offA[1] + kofs);
#pragma unroll
        for (int ii = 0; ii < 2; ii++)
            ldsm_x4(bf[2 * ii][0], bf[2 * ii][1], bf[2 * ii + 1][0],
                    bf[2 * ii + 1][1], bb0 + offB[ii] + kofs);
#pragma unroll
        for (int mi = 0; mi < 2; mi++)
#pragma unroll
            for (int ni = 0; ni < 4; ni++)
                mma_f16(acc[mi][ni], af[mi], bf[ni]);
    }

#pragma unroll
    for (int mi = 0; mi < 2; mi++)
#pragma unroll
        for (int ni = 0; ni < 4; ni++) {
            int r  = bm0 + wr * 32 + mi * 16 + g;
            int cc = wc * 32 + ni * 8 + c * 2;
            *reinterpret_cast<uint32_t*>(&C[(size_t)r * Nc + cc]) =
                pack_h2(acc[mi][ni][0], acc[mi][ni][1]);
            *reinterpret_cast<uint32_t*>(&C[(size_t)(r + 8) * Nc + cc]) =
                pack_h2(acc[mi][ni][2], acc[mi][ni][3]);
        }
}

// ---------------- z @ z^T: 4 column tiles per CTA, symmetric, streaming --------
// grid (32, 128): bi = blockIdx.y, bj0 = blockIdx.x*4; active iff bj0 <= bi.
__global__ void __launch_bounds__(256, 2)
k_zzt_h(const __half* __restrict__ Z, float* __restrict__ C) {
    constexpr int P = 72;
    const int bi  = blockIdx.y;
    const int bj0 = blockIdx.x * 4;
    if (bj0 > bi) return;
    const int nt = min(4, bi - bj0 + 1);   // tiles this CTA computes

    extern __shared__ __half smz[];
    __half* sAh = smz;
    __half* sBh = smz + 128 * P;
    const uint32_t smem_u32 = (uint32_t)__cvta_generic_to_shared(smz);

    const int tid  = threadIdx.x;
    const int warp = tid >> 5, lane = tid & 31;
    const int wm = warp & 1, wn = warp >> 1;
    const int g = lane >> 2, c = lane & 3;

    const int bm0 = bi * 128;
    const int bn0 = bj0 * 128;

    // A tile (128 rows at bm0)
#pragma unroll
    for (int i = 0; i < 4; i++) {
        int v = tid + i * 256;
        int r = v >> 3, ch = v & 7;
        cp16(smem_u32 + (uint32_t)(r * P + ch * 8) * 2u,
             Z + (size_t)(bm0 + r) * NZ_DIM + ch * 8);
    }
    // B tile (nt*128 rows at bn0)
    const int brows = nt * 128;
#pragma unroll
    for (int i = 0; i < 16; i++) {
        int v = tid + i * 256;
        int r = v >> 3, ch = v & 7;
        if (r < brows)
            cp16(smem_u32 + (uint32_t)(128 * P + r * P + ch * 8) * 2u,
                 Z + (size_t)(bn0 + r) * NZ_DIM + ch * 8);
    }
    cp_commit();
    cp_wait<0>();
    __syncthreads();

    for (int tile = 0; tile < nt; tile++) {
        const int bj = bj0 + tile;
        const int bncur = bj * 128;
        const __half* sB = sBh + tile * 128 * P;

        float acc[4][4][4];
#pragma unroll
        for (int mi = 0; mi < 4; mi++)
#pragma unroll
            for (int ni = 0; ni < 4; ni++)
#pragma unroll
                for (int j = 0; j < 4; j++) acc[mi][ni][j] = 0.f;

#pragma unroll
        for (int ks = 0; ks < 4; ks++) {
            const int k0 = ks * 16;
            uint32_t af[4][4];
            uint32_t bf[4][2];
#pragma unroll
            for (int mi = 0; mi < 4; mi++) {
                int r = wm * 64 + mi * 16 + g;
                af[mi][0] = *reinterpret_cast<const uint32_t*>(&sAh[r * P + k0 + 2 * c]);
                af[mi][1] = *reinterpret_cast<const uint32_t*>(&sAh[(r + 8) * P + k0 + 2 * c]);
                af[mi][2] = *reinterpret_cast<const uint32_t*>(&sAh[r * P + k0 + 2 * c + 8]);
                af[mi][3] = *reinterpret_cast<const uint32_t*>(&sAh[(r + 8) * P + k0 + 2 * c + 8]);
            }
#pragma unroll
            for (int ni = 0; ni < 4; ni++) {
                int n = wn * 32 + ni * 8 + g;
                bf[ni][0] = *reinterpret_cast<const uint32_t*>(&sB[n * P + k0 + 2 * c]);
                bf[ni][1] = *reinterpret_cast<const uint32_t*>(&sB[n * P + k0 + 2 * c + 8]);
            }
#pragma unroll
            for (int mi = 0; mi < 4; mi++)
#pragma unroll
                for (int ni = 0; ni < 4; ni++)
                    mma_f16(acc[mi][ni], af[mi], bf[ni]);
        }

        // direct store (rows bm0.., cols bncur..)
#pragma unroll
        for (int mi = 0; mi < 4; mi++)
#pragma unroll
            for (int ni = 0; ni < 4; ni++) {
                int r  = bm0 + wm * 64 + mi * 16 + g;
                int cc = bncur + wn * 32 + ni * 8 + c * 2;
                st_cs2(&C[(size_t)r * N_NODES + cc], acc[mi][ni][0], acc[mi][ni][1]);
                st_cs2(&C[(size_t)(r + 8) * N_NODES + cc], acc[mi][ni][2], acc[mi][ni][3]);
            }

        if (bi != bj) {
            // transposed store (rows bncur.., cols bm0..)
#pragma unroll
            for (int mi = 0; mi < 4; mi++)
#pragma unroll
                for (int ni = 0; ni < 4; ni++) {
                    int r  = bm0 + wm * 64 + mi * 16 + g;
                    int cc = bncur + wn * 32 + ni * 8 + c * 2;
                    st_cs1(&C[(size_t)cc * N_NODES + r],           acc[mi][ni][0]);
                    st_cs1(&C[(size_t)(cc + 1) * N_NODES + r],     acc[mi][ni][1]);
                    st_cs1(&C[(size_t)cc * N_NODES + r + 8],       acc[mi][ni][2]);
                    st_cs1(&C[(size_t)(cc + 1) * N_NODES + r + 8], acc[mi][ni][3]);
                }
        }
    }
}

// ---------------- stream/event singletons --------------------------------------
struct AuxRes {
    cudaStream_t s2;
    cudaEvent_t  evFork, evX, evJoin;
    AuxRes() {
        cudaStreamCreateWithFlags(&s2, cudaStreamNonBlocking);
        cudaEventCreateWithFlags(&evFork, cudaEventDisableTiming);
        cudaEventCreateWithFlags(&evX, cudaEventDisableTiming);
        cudaEventCreateWithFlags(&evJoin, cudaEventDisableTiming);
    }
};

// ---------------- launch --------------------------------------------------------
extern "C" void kernel_launch(void* const* d_in, const int* in_sizes, int n_in,
                              void* d_out, int out_size) {
    static AuxRes aux;

    const float* x  = (const float*)d_in[0];
    const float* W1 = (const float*)d_in[1];
    const float* W2 = (const float*)d_in[2];
    const float* ew = (const float*)d_in[3];
    const int*   ei = (const int*)d_in[4];

    float* out  = (float*)d_out;
    float* abar = out;
    float* z    = out + (size_t)N_NODES * N_NODES;

    __half *xh, *s1h, *h1h, *s2h, *w1t, *w2t, *zrh;
    cudaGetSymbolAddress((void**)&xh,  g_xh);
    cudaGetSymbolAddress((void**)&s1h, g_s1h);
    cudaGetSymbolAddress((void**)&h1h, g_h1h);
    cudaGetSymbolAddress((void**)&s2h, g_s2h);
    cudaGetSymbolAddress((void**)&w1t, g_w1t);
    cudaGetSymbolAddress((void**)&w2t, g_w2t);
    cudaGetSymbolAddress((void**)&zrh, g_zrh);

    constexpr int SM_G1  = 3 * 2 * 16384;                  // 98304
    constexpr int SM_G2  = (128 * 264 + 64 * 264) * 2;     // 101376
    constexpr int SM_ZZT = (128 + 512) * 72 * 2;           // 92160

    cudaFuncSetAttribute(k_gemm1hh,
                         cudaFuncAttributeMaxDynamicSharedMemorySize, SM_G1);
    cudaFuncSetAttribute(k_gemm2h,
                         cudaFuncAttributeMaxDynamicSharedMemorySize, SM_G2);
    cudaFuncSetAttribute(k_zzt_h,
                         cudaFuncAttributeMaxDynamicSharedMemorySize, SM_ZZT);

    // fork: side stream does x->fp16 convert then CSR chain
    cudaEventRecord(aux.evFork, 0);
    cudaStreamWaitEvent(aux.s2, aux.evFork, 0);

    k_transpose_h<<<dim3(H1_DIM / 32, F_IN / 32), dim3(32, 8)>>>(      // main
        W1, w1t, F_IN, H1_DIM);
    k_x2h<<<N_NODES * F_IN / 4 / 256, 256, 0, aux.s2>>>(               // s2
        (const float4*)x, (uint2*)xh);
    cudaEventRecord(aux.evX, aux.s2);
    k_transpose_h<<<dim3(NZ_DIM / 32, H1_DIM / 32), dim3(32, 8)>>>(    // main
        W2, w2t, H1_DIM, NZ_DIM);

    cudaStreamWaitEvent(0, aux.evX, 0);
    k_gemm1hh<<<dim3(H1_DIM / 128, N_NODES / 128), 256, SM_G1>>>(      // main
        xh, w1t, s1h);

    k_zero_counts<<<N_NODES / 1024, 256, 0, aux.s2>>>();               // s2
    k_hist<<<E_EDGES / 256, 256, 0, aux.s2>>>(ei);                     // s2
    k_scan<<<1, 256, 0, aux.s2>>>();                                   // s2
    k_scatter<<<E_EDGES / 256, 256, 0, aux.s2>>>(ei, ew);              // s2

    cudaEventRecord(aux.evJoin, aux.s2);
    cudaStreamWaitEvent(0, aux.evJoin, 0);

    k_spmm_relu_256h2<<<N_NODES / 2, 256>>>(                           // main
        (const __half2*)s1h, (__half2*)h1h);
    k_gemm2h<<<dim3(1, N_NODES / 128), 256, SM_G2>>>(h1h, w2t, s2h);   // main
    k_spmm_relu_64h2<<<N_NODES / 8, 256>>>(                            // main
        (const __half2*)s2h, (float2*)z, (__half2*)zrh);
    k_zzt_h<<<dim3(32, 128), 256, SM_ZZT>>>(zrh, abar);                // main
}

// round 16
// speedup vs baseline: 1.0134x; 1.0134x over previous
#include <cuda_runtime.h>
#include <cuda_fp16.h>
#include <cstdint>
#include <cstddef>

#define N_NODES 16384
#define E_EDGES 262144
#define F_IN    1024
#define H1_DIM  256
#define NZ_DIM  64

// ---------------- scratch ----------------------------------------------------
__device__ __half g_xh [N_NODES * F_IN];
__device__ __half g_s1h[N_NODES * H1_DIM];
__device__ __half g_h1h[N_NODES * H1_DIM];
__device__ __half g_s2h[N_NODES * NZ_DIM];
__device__ __half g_w1t[H1_DIM * F_IN];
__device__ __half g_w2t[NZ_DIM * H1_DIM];
__device__ __half g_zrh[N_NODES * NZ_DIM];
__device__ int    g_off   [N_NODES + 1];
__device__ int    g_cursor[N_NODES];
__device__ int2   g_srcw  [E_EDGES];

// ---------------- helpers -----------------------------------------------------
__device__ __forceinline__ void cp16(uint32_t s, const void* g) {
    asm volatile("cp.async.cg.shared.global [%0], [%1], 16;\n" ::"r"(s), "l"(g));
}
__device__ __forceinline__ void cp_commit() {
    asm volatile("cp.async.commit_group;\n");
}
template <int N>
__device__ __forceinline__ void cp_wait() {
    asm volatile("cp.async.wait_group %0;\n" ::"n"(N));
}
__device__ __forceinline__ uint32_t pack_h2(float lo, float hi) {
    __half2 h = __floats2half2_rn(lo, hi);
    return *reinterpret_cast<uint32_t*>(&h);
}
__device__ __forceinline__ void mma_f16(float (&d)[4], const uint32_t (&a)[4],
                                        const uint32_t (&b)[2]) {
    asm volatile(
        "mma.sync.aligned.m16n8k16.row.col.f32.f16.f16.f32 "
        "{%0,%1,%2,%3}, {%4,%5,%6,%7}, {%8,%9}, {%0,%1,%2,%3};"
        : "+f"(d[0]), "+f"(d[1]), "+f"(d[2]), "+f"(d[3])
        : "r"(a[0]), "r"(a[1]), "r"(a[2]), "r"(a[3]), "r"(b[0]), "r"(b[1]));
}
__device__ __forceinline__ void ldsm_x4(uint32_t& r0, uint32_t& r1,
                                        uint32_t& r2, uint32_t& r3, uint32_t a) {
    asm volatile("ldmatrix.sync.aligned.m8n8.x4.shared.b16 {%0,%1,%2,%3}, [%4];"
                 : "=r"(r0), "=r"(r1), "=r"(r2), "=r"(r3) : "r"(a));
}
__device__ __forceinline__ void st_cs1(float* p, float v) {
    asm volatile("st.global.cs.f32 [%0], %1;" ::"l"(p), "f"(v) : "memory");
}
__device__ __forceinline__ void st_cs2(float* p, float v0, float v1) {
    asm volatile("st.global.cs.v2.f32 [%0], {%1, %2};"
                 ::"l"(p), "f"(v0), "f"(v1) : "memory");
}

// ---------------- x -> fp16 convert --------------------------------------------
__global__ void k_x2h(const float4* __restrict__ in, uint2* __restrict__ out) {
    int i = blockIdx.x * blockDim.x + threadIdx.x;
    float4 v = in[i];
    out[i] = make_uint2(pack_h2(v.x, v.y), pack_h2(v.z, v.w));
}

// ---------------- CSR build ----------------------------------------------------
__global__ void k_zero_counts() {
    int i = blockIdx.x * blockDim.x + threadIdx.x;
    ((int4*)g_cursor)[i] = make_int4(0, 0, 0, 0);
}
__global__ void k_hist(const int* __restrict__ ei) {
    int e = blockIdx.x * blockDim.x + threadIdx.x;
    if (e < E_EDGES) atomicAdd(&g_cursor[ei[E_EDGES + e]], 1);
}
__global__ void k_scan() {
    __shared__ int part[256];
    const int t = threadIdx.x;
    const int base = t * (N_NODES / 256);
    int s = 0;
#pragma unroll
    for (int j = 0; j < N_NODES / 256; j++) s += g_cursor[base + j];
    part[t] = s;
    __syncthreads();
    for (int off = 1; off < 256; off <<= 1) {
        int v = (t >= off) ? part[t - off] : 0;
        __syncthreads();
        part[t] += v;
        __syncthreads();
    }
    int run = part[t] - s;
#pragma unroll
    for (int j = 0; j < N_NODES / 256; j++) {
        int idx = base + j;
        int c = g_cursor[idx];
        g_off[idx] = run;
        g_cursor[idx] = run;
        run += c;
    }
    if (t == 255) g_off[N_NODES] = run;
}
__global__ void k_scatter(const int* __restrict__ ei, const float* __restrict__ ew) {
    int e = blockIdx.x * blockDim.x + threadIdx.x;
    if (e < E_EDGES) {
        int d = ei[E_EDGES + e];
        int p = atomicAdd(&g_cursor[d], 1);
        g_srcw[p] = make_int2(ei[e], __float_as_int(ew[e]));
    }
}

// ---------------- weight transpose -> fp16 -------------------------------------
__global__ void k_transpose_h(const float* __restrict__ in, __half* __restrict__ out,
                              int R, int C) {
    __shared__ float tile[32][33];
    const int bx = blockIdx.x * 32;
    const int by = blockIdx.y * 32;
    const int x = threadIdx.x, y0 = threadIdx.y;
#pragma unroll
    for (int j = y0; j < 32; j += 8)
        tile[j][x] = in[(size_t)(by + j) * C + bx + x];
    __syncthreads();
#pragma unroll
    for (int j = y0; j < 32; j += 8)
        out[(size_t)(bx + j) * R + by + x] = __float2half_rn(tile[x][j]);
}

// ---------------- SpMM + ReLU (half2 lanes, fp32 accumulate) -------------------
__global__ void __launch_bounds__(256) k_spmm_relu_256h2(
    const __half2* __restrict__ in2, __half2* __restrict__ out2) {
    __shared__ int2 se[2][128];
    __shared__ int sdeg[2];
    const int t    = threadIdx.x;
    const int sub  = t >> 7;
    const int lane = t & 127;
    const int row  = blockIdx.x * 2 + sub;
    if (t < 2) sdeg[t] = g_off[blockIdx.x * 2 + t + 1] - g_off[blockIdx.x * 2 + t];
    __syncthreads();
    const int beg = g_off[row];
    const int deg = sdeg[sub];
    const int nch = (max(sdeg[0], sdeg[1]) + 127) >> 7;
    float ax = 0.f, ay = 0.f;
    for (int ch = 0; ch < nch; ch++) {
        int m = min(128, deg - ch * 128);
        __syncthreads();
        if (lane < m) se[sub][lane] = g_srcw[beg + ch * 128 + lane];
        __syncthreads();
        int j = 0;
        for (; j + 8 <= m; j += 8) {
            int2 v[8];
            float2 f[8];
#pragma unroll
            for (int u = 0; u < 8; u++) v[u] = se[sub][j + u];
#pragma unroll
            for (int u = 0; u < 8; u++)
                f[u] = __half22float2(__ldg(&in2[(size_t)v[u].x * 128 + lane]));
#pragma unroll
            for (int u = 0; u < 8; u++) {
                float w = __int_as_float(v[u].y);
                ax += w * f[u].x;
                ay += w * f[u].y;
            }
        }
        for (; j < m; j++) {
            int2 v = se[sub][j];
            float2 f = __half22float2(__ldg(&in2[(size_t)v.x * 128 + lane]));
            float w = __int_as_float(v.y);
            ax += w * f.x;
            ay += w * f.y;
        }
    }
    out2[(size_t)row * 128 + lane] = __floats2half2_rn(fmaxf(ax, 0.f), fmaxf(ay, 0.f));
}

__global__ void __launch_bounds__(256) k_spmm_relu_64h2(
    const __half2* __restrict__ in2, float2* __restrict__ out2,
    __half2* __restrict__ outr2) {
    __shared__ int2 se[8][32];
    __shared__ int sdeg[8];
    const int t    = threadIdx.x;
    const int sub  = t >> 5;
    const int lane = t & 31;
    const int row  = blockIdx.x * 8 + sub;
    if (t < 8) sdeg[t] = g_off[blockIdx.x * 8 + t + 1] - g_off[blockIdx.x * 8 + t];
    __syncthreads();
    const int beg = g_off[row];
    const int deg = sdeg[sub];
    int mx = sdeg[0];
#pragma unroll
    for (int q = 1; q < 8; q++) mx = max(mx, sdeg[q]);
    const int nch = (mx + 31) >> 5;
    float ax = 0.f, ay = 0.f;
    for (int ch = 0; ch < nch; ch++) {
        int m = min(32, deg - ch * 32);
        __syncthreads();
        if (lane < m) se[sub][lane] = g_srcw[beg + ch * 32 + lane];
        __syncthreads();
        int j = 0;
        for (; j + 8 <= m; j += 8) {
            int2 v[8];
            float2 f[8];
#pragma unroll
            for (int u = 0; u < 8; u++) v[u] = se[sub][j + u];
#pragma unroll
            for (int u = 0; u < 8; u++)
                f[u] = __half22float2(__ldg(&in2[(size_t)v[u].x * 32 + lane]));
#pragma unroll
            for (int u = 0; u < 8; u++) {
                float w = __int_as_float(v[u].y);
                ax += w * f[u].x;
                ay += w * f[u].y;
            }
        }
        for (; j < m; j++) {
            int2 v = se[sub][j];
            float2 f = __half22float2(__ldg(&in2[(size_t)v.x * 32 + lane]));
            float w = __int_as_float(v.y);
            ax += w * f.x;
            ay += w * f.y;
        }
    }
    float rx = fmaxf(ax, 0.f), ry = fmaxf(ay, 0.f);
    out2 [(size_t)row * 32 + lane] = make_float2(rx, ry);
    outr2[(size_t)row * 32 + lane] = __floats2half2_rn(rx, ry);
}

// ---------------- gemm1: BM=128 BN=128 BK=64, SW128 swizzle, 3 stages -----------
__global__ void __launch_bounds__(256, 2)
k_gemm1hh(const __half* __restrict__ A, const __half* __restrict__ Bt,
          __half* __restrict__ C) {
    constexpr int K = F_IN, Nc = H1_DIM;
    constexpr int STAGE = 16384;
    constexpr int STG = 3;
    constexpr int NT = K / 64;

    extern __shared__ __half smh[];
    const uint32_t smem_u32 = (uint32_t)__cvta_generic_to_shared(smh);
    const uint32_t bb0 = smem_u32 + STG * STAGE;

    const int tid  = threadIdx.x;
    const int warp = tid >> 5, lane = tid & 31;
    const int wr = warp >> 1, wc = warp & 1;
    const int bm0 = blockIdx.y * 128, bn0 = blockIdx.x * 128;
    const int g = lane >> 2, c = lane & 3;

    const int lr = lane & 7, q = lane >> 3;
    uint32_t baseA[2], colA, xormA[2];
#pragma unroll
    for (int mi = 0; mi < 2; mi++) {
        int row = wr * 32 + mi * 16 + lr + (q & 1) * 8;
        baseA[mi] = (uint32_t)row * 128u;
        xormA[mi] = (uint32_t)((row & 7) << 4);
    }
    colA = (uint32_t)((q >> 1) * 16);
    uint32_t baseB[4], colB, xormB[4];
#pragma unroll
    for (int ii = 0; ii < 4; ii++) {
        int row = wc * 64 + (2 * ii + (q >> 1)) * 8 + lr;
        baseB[ii] = (uint32_t)row * 128u;
        xormB[ii] = (uint32_t)((row & 7) << 4);
    }
    colB = (uint32_t)((q & 1) * 16);

    float acc[2][8][4];
#pragma unroll
    for (int mi = 0; mi < 2; mi++)
#pragma unroll
        for (int ni = 0; ni < 8; ni++)
#pragma unroll
            for (int j = 0; j < 4; j++) acc[mi][ni][j] = 0.f;

    auto load_tiles = [&](int kt, int st) {
        const __half* Ag = A + (size_t)bm0 * K + kt * 64;
        uint32_t abase = smem_u32 + (uint32_t)(st * STAGE);
#pragma unroll
        for (int i = 0; i < 4; i++) {
            int v = tid + i * 256;
            int r = v >> 3, ch = v & 7;
            uint32_t off = (uint32_t)(r * 128 + ch * 16);
            uint32_t sw  = off ^ (uint32_t)((r & 7) << 4);
            cp16(abase + sw, Ag + (size_t)r * K + ch * 8);
        }
        const __half* Bg = Bt + (size_t)bn0 * K + kt * 64;
        uint32_t bbase = bb0 + (uint32_t)(st * STAGE);
#pragma unroll
        for (int i = 0; i < 4; i++) {
            int v = tid + i * 256;
            int r = v >> 3, ch = v & 7;
            uint32_t off = (uint32_t)(r * 128 + ch * 16);
            uint32_t sw  = off ^ (uint32_t)((r & 7) << 4);
            cp16(bbase + sw, Bg + (size_t)r * K + ch * 8);
        }
    };

    load_tiles(0, 0);
    cp_commit();
    load_tiles(1, 1);
    cp_commit();

    int st = 0;
    for (int kt = 0; kt < NT; kt++) {
        cp_wait<1>();
        __syncthreads();

        int pf = kt + 2;
        if (pf < NT) load_tiles(pf, (st + 2) % STG);
        cp_commit();

        uint32_t abase = smem_u32 + (uint32_t)(st * STAGE);
        uint32_t bbase = bb0 + (uint32_t)(st * STAGE);
#pragma unroll
        for (int ks = 0; ks < 4; ks++) {
            const uint32_t kofs = ks * 32;
            uint32_t af[2][4];
            uint32_t bf[8][2];
#pragma unroll
            for (int mi = 0; mi < 2; mi++)
                ldsm_x4(af[mi][0], af[mi][1], af[mi][2], af[mi][3],
                        abase + baseA[mi] + ((colA + kofs) ^ xormA[mi]));
#pragma unroll
            for (int ii = 0; ii < 4; ii++)
                ldsm_x4(bf[2 * ii][0], bf[2 * ii][1], bf[2 * ii + 1][0],
                        bf[2 * ii + 1][1],
                        bbase + baseB[ii] + ((colB + kofs) ^ xormB[ii]));
#pragma unroll
            for (int mi = 0; mi < 2; mi++)
#pragma unroll
                for (int ni = 0; ni < 8; ni++)
                    mma_f16(acc[mi][ni], af[mi], bf[ni]);
        }
        st = (st + 1) % STG;
    }

    __syncthreads();
#pragma unroll
    for (int mi = 0; mi < 2; mi++)
#pragma unroll
        for (int ni = 0; ni < 8; ni++) {
            int r  = bm0 + wr * 32 + mi * 16 + g;
            int cc = bn0 + wc * 64 + ni * 8 + c * 2;
            *reinterpret_cast<uint32_t*>(&C[(size_t)r * Nc + cc]) =
                pack_h2(acc[mi][ni][0], acc[mi][ni][1]);
            *reinterpret_cast<uint32_t*>(&C[(size_t)(r + 8) * Nc + cc]) =
                pack_h2(acc[mi][ni][2], acc[mi][ni][3]);
        }
}

// ---------------- gemm2: single-shot (full K in smem, no loop barriers) --------
__global__ void __launch_bounds__(256, 2)
k_gemm2h(const __half* __restrict__ A, const __half* __restrict__ Bt,
         __half* __restrict__ C) {
    constexpr int K = H1_DIM, Nc = NZ_DIM;
    constexpr int P = 264;

    extern __shared__ __half smh[];
    const uint32_t smem_u32 = (uint32_t)__cvta_generic_to_shared(smh);
    const uint32_t bb0 = smem_u32 + (uint32_t)(128 * P) * 2u;

    const int tid  = threadIdx.x;
    const int warp = tid >> 5, lane = tid & 31;
    const int wr = warp >> 1, wc = warp & 1;
    const int bm0 = blockIdx.y * 128;
    const int g = lane >> 2, c = lane & 3;

    const int lr = lane & 7, q = lane >> 3;
    uint32_t offA[2], offB[2];
#pragma unroll
    for (int mi = 0; mi < 2; mi++) {
        int row = wr * 32 + mi * 16 + lr + (q & 1) * 8;
        int col = (q >> 1) * 8;
        offA[mi] = (uint32_t)(row * P + col) * 2u;
    }
#pragma unroll
    for (int ii = 0; ii < 2; ii++) {
        int row = wc * 32 + (2 * ii + (q >> 1)) * 8 + lr;
        int col = (q & 1) * 8;
        offB[ii] = (uint32_t)(row * P + col) * 2u;
    }

    {
        const __half* Ag = A + (size_t)bm0 * K;
#pragma unroll
        for (int i = 0; i < 16; i++) {
            int v = tid + i * 256;
            int r = v >> 5, ch = v & 31;
            cp16(smem_u32 + (uint32_t)(r * P + ch * 8) * 2u,
                 Ag + (size_t)r * K + ch * 8);
        }
#pragma unroll
        for (int i = 0; i < 8; i++) {
            int v = tid + i * 256;
            int r = v >> 5, ch = v & 31;
            cp16(bb0 + (uint32_t)(r * P + ch * 8) * 2u,
                 Bt + (size_t)r * K + ch * 8);
        }
    }
    cp_commit();

    float acc[2][4][4];
#pragma unroll
    for (int mi = 0; mi < 2; mi++)
#pragma unroll
        for (int ni = 0; ni < 4; ni++)
#pragma unroll
            for (int j = 0; j < 4; j++) acc[mi][ni][j] = 0.f;

    cp_wait<0>();
    __syncthreads();

#pragma unroll
    for (int kk = 0; kk < K / 16; kk++) {
        const uint32_t kofs = (uint32_t)(kk * 16) * 2u;
        uint32_t af[2][4];
        uint32_t bf[4][2];
        ldsm_x4(af[0][0], af[0][1], af[0][2], af[0][3],
                smem_u32 + offA[0] + kofs);
        ldsm_x4(af[1][0], af[1][1], af[1][2], af[1][3],
                smem_u32 + offA[1] + kofs);
#pragma unroll
        for (int ii = 0; ii < 2; ii++)
            ldsm_x4(bf[2 * ii][0], bf[2 * ii][1], bf[2 * ii + 1][0],
                    bf[2 * ii + 1][1], bb0 + offB[ii] + kofs);
#pragma unroll
        for (int mi = 0; mi < 2; mi++)
#pragma unroll
            for (int ni = 0; ni < 4; ni++)
                mma_f16(acc[mi][ni], af[mi], bf[ni]);
    }

#pragma unroll
    for (int mi = 0; mi < 2; mi++)
#pragma unroll
        for (int ni = 0; ni < 4; ni++) {
            int r  = bm0 + wr * 32 + mi * 16 + g;
            int cc = wc * 32 + ni * 8 + c * 2;
            *reinterpret_cast<uint32_t*>(&C[(size_t)r * Nc + cc]) =
                pack_h2(acc[mi][ni][0], acc[mi][ni][1]);
            *reinterpret_cast<uint32_t*>(&C[(size_t)(r + 8) * Nc + cc]) =
                pack_h2(acc[mi][ni][2], acc[mi][ni][3]);
        }
}

// ---------------- z @ z^T: 2 column tiles per CTA, symmetric, streaming --------
// grid (64, 128): bi = blockIdx.y, bj0 = blockIdx.x*2; active iff bj0 <= bi.
__global__ void __launch_bounds__(256, 2)
k_zzt_h(const __half* __restrict__ Z, float* __restrict__ C) {
    constexpr int P = 72;
    const int bi  = blockIdx.y;
    const int bj0 = blockIdx.x * 2;
    if (bj0 > bi) return;
    const bool has1 = (bj0 + 1 <= bi);

    extern __shared__ __half smz[];
    __half* sAh = smz;
    __half* sBh = smz + 128 * P;
    const uint32_t smem_u32 = (uint32_t)__cvta_generic_to_shared(smz);

    const int tid  = threadIdx.x;
    const int warp = tid >> 5, lane = tid & 31;
    const int wm = warp & 1, wn = warp >> 1;
    const int g = lane >> 2, c = lane & 3;

    const int bm0 = bi * 128;
    const int bn0 = bj0 * 128;

#pragma unroll
    for (int i = 0; i < 4; i++) {
        int v = tid + i * 256;
        int r = v >> 3, ch = v & 7;
        cp16(smem_u32 + (uint32_t)(r * P + ch * 8) * 2u,
             Z + (size_t)(bm0 + r) * NZ_DIM + ch * 8);
    }
    const int brows = has1 ? 256 : 128;
#pragma unroll
    for (int i = 0; i < 8; i++) {
        int v = tid + i * 256;
        int r = v >> 3, ch = v & 7;
        if (r < brows)
            cp16(smem_u32 + (uint32_t)(128 * P + r * P + ch * 8) * 2u,
                 Z + (size_t)(bn0 + r) * NZ_DIM + ch * 8);
    }
    cp_commit();
    cp_wait<0>();
    __syncthreads();

    for (int tile = 0; tile < (has1 ? 2 : 1); tile++) {
        const int bj = bj0 + tile;
        const int bncur = bj * 128;
        const __half* sB = sBh + tile * 128 * P;

        float acc[4][4][4];
#pragma unroll
        for (int mi = 0; mi < 4; mi++)
#pragma unroll
            for (int ni = 0; ni < 4; ni++)
#pragma unroll
                for (int j = 0; j < 4; j++) acc[mi][ni][j] = 0.f;

#pragma unroll
        for (int ks = 0; ks < 4; ks++) {
            const int k0 = ks * 16;
            uint32_t af[4][4];
            uint32_t bf[4][2];
#pragma unroll
            for (int mi = 0; mi < 4; mi++) {
                int r = wm * 64 + mi * 16 + g;
                af[mi][0] = *reinterpret_cast<const uint32_t*>(&sAh[r * P + k0 + 2 * c]);
                af[mi][1] = *reinterpret_cast<const uint32_t*>(&sAh[(r + 8) * P + k0 + 2 * c]);
                af[mi][2] = *reinterpret_cast<const uint32_t*>(&sAh[r * P + k0 + 2 * c + 8]);
                af[mi][3] = *reinterpret_cast<const uint32_t*>(&sAh[(r + 8) * P + k0 + 2 * c + 8]);
            }
#pragma unroll
            for (int ni = 0; ni < 4; ni++) {
                int n = wn * 32 + ni * 8 + g;
                bf[ni][0] = *reinterpret_cast<const uint32_t*>(&sB[n * P + k0 + 2 * c]);
                bf[ni][1] = *reinterpret_cast<const uint32_t*>(&sB[n * P + k0 + 2 * c + 8]);
            }
#pragma unroll
            for (int mi = 0; mi < 4; mi++)
#pragma unroll
                for (int ni = 0; ni < 4; ni++)
                    mma_f16(acc[mi][ni], af[mi], bf[ni]);
        }

        // direct store (rows bm0.., cols bncur..)
#pragma unroll
        for (int mi = 0; mi < 4; mi++)
#pragma unroll
            for (int ni = 0; ni < 4; ni++) {
                int r  = bm0 + wm * 64 + mi * 16 + g;
                int cc = bncur + wn * 32 + ni * 8 + c * 2;
                st_cs2(&C[(size_t)r * N_NODES + cc], acc[mi][ni][0], acc[mi][ni][1]);
                st_cs2(&C[(size_t)(r + 8) * N_NODES + cc], acc[mi][ni][2], acc[mi][ni][3]);
            }

        if (bi != bj) {
            // transposed store (rows bncur.., cols bm0..)
#pragma unroll
            for (int mi = 0; mi < 4; mi++)
#pragma unroll
                for (int ni = 0; ni < 4; ni++) {
                    int r  = bm0 + wm * 64 + mi * 16 + g;
                    int cc = bncur + wn * 32 + ni * 8 + c * 2;
                    st_cs1(&C[(size_t)cc * N_NODES + r],           acc[mi][ni][0]);
                    st_cs1(&C[(size_t)(cc + 1) * N_NODES + r],     acc[mi][ni][1]);
                    st_cs1(&C[(size_t)cc * N_NODES + r + 8],       acc[mi][ni][2]);
                    st_cs1(&C[(size_t)(cc + 1) * N_NODES + r + 8], acc[mi][ni][3]);
                }
        }
    }
}

// ---------------- stream/event singletons --------------------------------------
struct AuxRes {
    cudaStream_t s2;
    cudaEvent_t  evFork, evX, evJoin;
    AuxRes() {
        cudaStreamCreateWithFlags(&s2, cudaStreamNonBlocking);
        cudaEventCreateWithFlags(&evFork, cudaEventDisableTiming);
        cudaEventCreateWithFlags(&evX, cudaEventDisableTiming);
        cudaEventCreateWithFlags(&evJoin, cudaEventDisableTiming);
    }
};

// ---------------- launch --------------------------------------------------------
extern "C" void kernel_launch(void* const* d_in, const int* in_sizes, int n_in,
                              void* d_out, int out_size) {
    static AuxRes aux;

    const float* x  = (const float*)d_in[0];
    const float* W1 = (const float*)d_in[1];
    const float* W2 = (const float*)d_in[2];
    const float* ew = (const float*)d_in[3];
    const int*   ei = (const int*)d_in[4];

    float* out  = (float*)d_out;
    float* abar = out;
    float* z    = out + (size_t)N_NODES * N_NODES;

    __half *xh, *s1h, *h1h, *s2h, *w1t, *w2t, *zrh;
    cudaGetSymbolAddress((void**)&xh,  g_xh);
    cudaGetSymbolAddress((void**)&s1h, g_s1h);
    cudaGetSymbolAddress((void**)&h1h, g_h1h);
    cudaGetSymbolAddress((void**)&s2h, g_s2h);
    cudaGetSymbolAddress((void**)&w1t, g_w1t);
    cudaGetSymbolAddress((void**)&w2t, g_w2t);
    cudaGetSymbolAddress((void**)&zrh, g_zrh);

    constexpr int SM_G1  = 3 * 2 * 16384;                  // 98304
    constexpr int SM_G2  = (128 * 264 + 64 * 264) * 2;     // 101376
    constexpr int SM_ZZT = (128 + 256) * 72 * 2;           // 55296

    cudaFuncSetAttribute(k_gemm1hh,
                         cudaFuncAttributeMaxDynamicSharedMemorySize, SM_G1);
    cudaFuncSetAttribute(k_gemm2h,
                         cudaFuncAttributeMaxDynamicSharedMemorySize, SM_G2);
    cudaFuncSetAttribute(k_zzt_h,
                         cudaFuncAttributeMaxDynamicSharedMemorySize, SM_ZZT);

    // fork: side stream does x->fp16 convert then CSR chain
    cudaEventRecord(aux.evFork, 0);
    cudaStreamWaitEvent(aux.s2, aux.evFork, 0);

    k_transpose_h<<<dim3(H1_DIM / 32, F_IN / 32), dim3(32, 8)>>>(      // main
        W1, w1t, F_IN, H1_DIM);
    k_x2h<<<N_NODES * F_IN / 4 / 256, 256, 0, aux.s2>>>(               // s2
        (const float4*)x, (uint2*)xh);
    cudaEventRecord(aux.evX, aux.s2);
    k_transpose_h<<<dim3(NZ_DIM / 32, H1_DIM / 32), dim3(32, 8)>>>(    // main
        W2, w2t, H1_DIM, NZ_DIM);

    cudaStreamWaitEvent(0, aux.evX, 0);
    k_gemm1hh<<<dim3(H1_DIM / 128, N_NODES / 128), 256, SM_G1>>>(      // main
        xh, w1t, s1h);

    k_zero_counts<<<N_NODES / 1024, 256, 0, aux.s2>>>();               // s2
    k_hist<<<E_EDGES / 256, 256, 0, aux.s2>>>(ei);                     // s2
    k_scan<<<1, 256, 0, aux.s2>>>();                                   // s2
    k_scatter<<<E_EDGES / 256, 256, 0, aux.s2>>>(ei, ew);              // s2

    cudaEventRecord(aux.evJoin, aux.s2);
    cudaStreamWaitEvent(0, aux.evJoin, 0);

    k_spmm_relu_256h2<<<N_NODES / 2, 256>>>(                           // main
        (const __half2*)s1h, (__half2*)h1h);
    k_gemm2h<<<dim3(1, N_NODES / 128), 256, SM_G2>>>(h1h, w2t, s2h);   // main
    k_spmm_relu_64h2<<<N_NODES / 8, 256>>>(                            // main
        (const __half2*)s2h, (float2*)z, (__half2*)zrh);
    k_zzt_h<<<dim3(64, 128), 256, SM_ZZT>>>(zrh, abar);                // main
}